// round 11
// baseline (speedup 1.0000x reference)
#include <cuda_runtime.h>
#include <math.h>
#include <stdint.h>
typedef unsigned long long ull;
typedef uint32_t u32;

#define NTHR 512
#define HB   32768
#define WB_F 16384                 // weight smem offset in floats (64KB)
#define SMEM_BYTES 131072

__device__ float g_X[(size_t)512 * 64 * 1024];      // x@W0[:512], row-major [t*64+b][1024]
__device__ float g_T[8][HB];                        // transposed states [slot][col][64]; 7=hT
__device__ float g_W2[(size_t)576 * 8192];          // [(jt*9+g)][k][ch][8]
__device__ unsigned int g_arr[2], g_gen[2];

__device__ __forceinline__ void fma2(ull &d, ull a, ull b) {
    asm("fma.rn.f32x2 %0, %1, %2, %0;" : "+l"(d) : "l"(a), "l"(b));
}
__device__ __forceinline__ ull dup2(float v) {
    ull r; asm("mov.b64 %0, {%1, %1};" : "=l"(r) : "f"(v)); return r;
}
__device__ __forceinline__ float2 unpk(ull v) {
    float2 f; asm("mov.b64 {%0, %1}, %2;" : "=f"(f.x), "=f"(f.y) : "l"(v)); return f;
}
__device__ __forceinline__ u32 smem_u32(const void* p) {
    u32 a; asm("{ .reg .u64 t; cvta.to.shared.u64 t, %1; cvt.u32.u64 %0, t; }" : "=r"(a) : "l"(p));
    return a;
}
__device__ __forceinline__ void cp16(u32 d, const void* s) {
    asm volatile("cp.async.cg.shared.global [%0], [%1], 16;" :: "r"(d), "l"(s) : "memory");
}
__device__ __forceinline__ float ldcg(const float* p) {
    float v; asm("ld.global.cg.f32 %0, [%1];" : "=f"(v) : "l"(p)); return v;
}
__device__ __forceinline__ void grid_bar(int dom) {
    __syncthreads();
    if (threadIdx.x == 0) {
        unsigned int gen = ((volatile unsigned int*)&g_gen[dom])[0];
        __threadfence();
        if (atomicAdd(&g_arr[dom], 1u) == 63u) {
            g_arr[dom] = 0u; __threadfence();
            ((volatile unsigned int*)&g_gen[dom])[0] = gen + 1u;
        } else {
            while (((volatile unsigned int*)&g_gen[dom])[0] == gen) { }
        }
        __threadfence();
    }
    __syncthreads();
}
__device__ __forceinline__ float actf(int a, float x) {
    if (a == 0) return tanhf(x);
    if (a == 1) return fmaxf(x, 0.f);
    if (a == 2) return 1.f / (1.f + expf(-x));
    return x;
}

// ---------- prep: weight pack + hidden transpose + X precompute ----------
__global__ void __launch_bounds__(256) prep_kernel(const float* __restrict__ A,
    const float* __restrict__ hid, const float* __restrict__ W0, const float* __restrict__ Ws) {
    int bid = blockIdx.x, tid = threadIdx.x;
    if (bid < 576) {                       // pack: bid = jt*9+g
        int jt = bid / 9, g = bid % 9;
        const float* src = (g == 8) ? (W0 + (size_t)512 * 1024) : (Ws + (size_t)g * 512 * 1024);
        float* dst = g_W2 + (size_t)bid * 8192;
#pragma unroll
        for (int it = 0; it < 8; ++it) {
            int d4 = (tid + it * 256) * 4;
            int k = d4 >> 4, ch = (d4 >> 3) & 1, jc = d4 & 7;
            *(float4*)(dst + d4) = *(const float4*)(src + (size_t)k * 1024 + ch * 512 + jt * 8 + jc);
        }
        return;
    }
    if (bid == 576) {                      // hT init
        for (int i = tid; i < HB; i += 256)
            g_T[7][i] = hid[(size_t)(i & 63) * 512 + (i >> 6)];
        return;
    }
    // X = inputs @ W0[:512]
    int idx = bid - 577;
    __shared__ ull   AsD[64][17];
    __shared__ float Bs[16][68];
    const int n0 = (idx & 15) * 64, m0 = (idx >> 4) * 64;
    const int tx = tid & 15, ty = tid >> 4;
    ull acc[4][2];
#pragma unroll
    for (int i = 0; i < 4; ++i) { acc[i][0] = 0; acc[i][1] = 0; }
    for (int k0 = 0; k0 < 512; k0 += 16) {
        {
            int am = tid >> 2, a4 = tid & 3;
            float4 v = *(const float4*)(A + (size_t)(m0 + am) * 512 + k0 + a4 * 4);
            AsD[am][a4*4+0]=dup2(v.x); AsD[am][a4*4+1]=dup2(v.y);
            AsD[am][a4*4+2]=dup2(v.z); AsD[am][a4*4+3]=dup2(v.w);
        }
        {
            int bk = tid >> 4, b4 = tid & 15;
            *(float4*)&Bs[bk][b4*4] = *(const float4*)(W0 + (size_t)(k0+bk)*1024 + n0 + b4*4);
        }
        __syncthreads();
#pragma unroll
        for (int k = 0; k < 16; ++k) {
            ulonglong2 b = *(const ulonglong2*)&Bs[k][tx*4];
#pragma unroll
            for (int i = 0; i < 4; ++i) { ull a = AsD[ty*4+i][k]; fma2(acc[i][0],a,b.x); fma2(acc[i][1],a,b.y); }
        }
        __syncthreads();
    }
#pragma unroll
    for (int i = 0; i < 4; ++i) {
        float2 lo = unpk(acc[i][0]), hi = unpk(acc[i][1]);
        *(float4*)(g_X + (size_t)(m0+ty*4+i)*1024 + n0 + tx*4) = make_float4(lo.x,lo.y,hi.x,hi.y);
    }
}

// ---------- one DAG level ----------
// CTA: rows rg*32..+32 (lane=row), cols jt*8..+8. Warps: jq=w&1 (4 cols), kq=w>>1 (8 K-segs).
template<int NG, int NP, bool P0B, bool P3M>
__device__ __forceinline__ void phase(float* sm, u32 smb, int rg, int jt, int t,
    const int* gis, const int* pps, const int* acts, const int* dss,
    const float* pred0, const float* pred1, float* out)
{
    const int tid = threadIdx.x, lane = tid & 31, w = tid >> 5;
    const int jq = w & 1, kq = w >> 1;
    const int jc0 = jt * 8 + jq * 4;
    const int row = rg * 32 + lane;
    const bool epi = (w < 2);

    float pre_sp[NP][4], pre_b[8], pre_m[4];
    if (epi) {
#pragma unroll
        for (int p = 0; p < NP; ++p)
#pragma unroll
            for (int cc = 0; cc < 4; ++cc)
                pre_sp[p][cc] = ldcg((p ? pred1 : pred0) + (jc0 + cc) * 64 + row);
        if (P0B)
#pragma unroll
            for (int cc = 0; cc < 4; ++cc) {
                pre_b[cc]   = ldcg(g_X + ((size_t)t*64 + row)*1024 + jc0 + cc);
                pre_b[4+cc] = ldcg(g_X + ((size_t)t*64 + row)*1024 + 512 + jc0 + cc);
            }
        if (P3M)
#pragma unroll
            for (int cc = 0; cc < 4; ++cc) {
                float m = 0.f;
#pragma unroll
                for (int st = 1; st <= 6; ++st) m += ldcg(&g_T[st][(jc0+cc)*64 + row]);
                pre_m[cc] = m;
            }
    }

    auto stage = [&](int c, int buf) {
#pragma unroll
        for (int it = 0; it < NP * 2; ++it) {
            int i = tid + it * NTHR, p = i >> 10, rem = i & 1023, kl = rem >> 3, seg = rem & 7;
            const float* s = (p ? pred1 : pred0) + (size_t)(c*128 + kl)*64 + rg*32 + seg*4;
            cp16(smb + (u32)(((buf*2 + p)*4096 + kl*32 + seg*4) * 4), s);
        }
#pragma unroll
        for (int it = 0; it < NG; ++it) {
            int i = tid + it * NTHR, g = i >> 9, rem = i & 511;
            const float* s = g_W2 + (size_t)(jt*9 + gis[g])*8192 + c*2048 + rem*4;
            cp16(smb + (u32)((WB_F + (buf*NG + g)*2048 + rem*4) * 4), s);
        }
        asm volatile("cp.async.commit_group;" ::: "memory");
    };

    ull acc[NG][2][2];
#pragma unroll
    for (int g = 0; g < NG; ++g)
#pragma unroll
        for (int ch = 0; ch < 2; ++ch) { acc[g][ch][0] = 0; acc[g][ch][1] = 0; }

    stage(0, 0);
    for (int c = 0; c < 4; ++c) {
        asm volatile("cp.async.wait_group 0;" ::: "memory");
        __syncthreads();
        if (c < 3) stage(c + 1, (c + 1) & 1);
        const float* s0p = sm + ((c & 1)*2 + 0)*4096 + kq*512 + lane;
        const float* s1p = s0p + 4096;
        const float* wbF = sm + WB_F + (c & 1)*NG*2048 + kq*256 + jq*4;
#pragma unroll
        for (int kk = 0; kk < 16; ++kk) {
            ull sd0 = dup2(s0p[kk * 32]);
            ull sd1 = (NP == 2) ? dup2(s1p[kk * 32]) : 0ull;
#pragma unroll
            for (int g = 0; g < NG; ++g) {
                const float* wp = wbF + g*2048 + kk*16;
                ulonglong2 wc = *(const ulonglong2*)(wp);
                ulonglong2 wh = *(const ulonglong2*)(wp + 8);
                ull sd = (NP == 2 && pps[g]) ? sd1 : sd0;
                fma2(acc[g][0][0], sd, wc.x); fma2(acc[g][0][1], sd, wc.y);
                fma2(acc[g][1][0], sd, wh.x); fma2(acc[g][1][1], sd, wh.y);
            }
        }
        __syncthreads();
    }

    // reduce over 8 K-segments
    ull* red = (ull*)sm;
    const int stride = NG * 4 + 1;
    if (kq) {
        ull* rp = red + (size_t)((kq - 1)*64 + jq*32 + lane) * stride;
#pragma unroll
        for (int g = 0; g < NG; ++g)
#pragma unroll
            for (int ch = 0; ch < 2; ++ch)
#pragma unroll
                for (int jp = 0; jp < 2; ++jp) rp[(g*2 + ch)*2 + jp] = acc[g][ch][jp];
    }
    __syncthreads();
    if (epi) {
        float av[NG][2][4];
#pragma unroll
        for (int g = 0; g < NG; ++g)
#pragma unroll
            for (int ch = 0; ch < 2; ++ch)
#pragma unroll
                for (int jp = 0; jp < 2; ++jp) {
                    float2 v = unpk(acc[g][ch][jp]);
                    av[g][ch][jp*2] = v.x; av[g][ch][jp*2+1] = v.y;
                }
#pragma unroll
        for (int q = 0; q < 7; ++q) {
            const ull* rp = red + (size_t)(q*64 + jq*32 + lane) * stride;
#pragma unroll
            for (int g = 0; g < NG; ++g)
#pragma unroll
                for (int ch = 0; ch < 2; ++ch)
#pragma unroll
                    for (int jp = 0; jp < 2; ++jp) {
                        float2 v = unpk(rp[(g*2 + ch)*2 + jp]);
                        av[g][ch][jp*2] += v.x; av[g][ch][jp*2+1] += v.y;
                    }
        }
        float mv[4] = {0.f, 0.f, 0.f, 0.f};
#pragma unroll
        for (int g = 0; g < NG; ++g) {
#pragma unroll
            for (int cc = 0; cc < 4; ++cc) {
                float cs = av[g][0][cc], hs = av[g][1][cc];
                if (P0B) { cs += pre_b[cc]; hs += pre_b[4 + cc]; }
                float sp = pre_sp[(NP == 2) ? pps[g] : 0][cc];
                float cg = 1.f / (1.f + expf(-cs));
                float hv = actf(acts[g], hs);
                float nv = sp + cg * (hv - sp);
                if (!P3M) g_T[dss[g]][(jc0 + cc)*64 + row] = nv;
                else mv[cc] += nv;
            }
        }
        if (P3M) {
#pragma unroll
            for (int cc = 0; cc < 4; ++cc) {
                float m = (pre_m[cc] + mv[cc]) * 0.125f;
                out[(size_t)t*HB + (size_t)row*512 + jc0 + cc] = m;
                g_T[7][(jc0 + cc)*64 + row] = m;
            }
        }
    }
}

__global__ void __launch_bounds__(NTHR, 1) recurrent_kernel(float* __restrict__ out, int tail)
{
    extern __shared__ float sm[];
    u32 smb = smem_u32(sm);
    const int bid = blockIdx.x, rg = bid >> 6, jt = bid & 63;
    float* T = &g_T[0][0];
    const int gi0[1]={8},       pp0[1]={0},       ac0[1]={0},       ds0[1]={0};
    const int gi1[2]={0,1},     pp1[2]={0,0},     ac1[2]={0,1},     ds1[2]={1,2};
    const int gi2[4]={2,3,4,5}, pp2[4]={0,0,1,1}, ac2[4]={2,3,0,1}, ds2[4]={3,4,5,6};
    const int gi3[2]={6,7},     pp3[2]={0,1},     ac3[2]={2,3},     ds3[2]={0,0};

    for (int t = 0; t < 512; ++t) {
        phase<1,1,true ,false>(sm,smb,rg,jt,t, gi0,pp0,ac0,ds0, T+7*HB, nullptr, out);
        grid_bar(rg);
        phase<2,1,false,false>(sm,smb,rg,jt,t, gi1,pp1,ac1,ds1, T+0*HB, nullptr, out);
        grid_bar(rg);
        phase<4,2,false,false>(sm,smb,rg,jt,t, gi2,pp2,ac2,ds2, T+1*HB, T+2*HB, out);
        grid_bar(rg);
        phase<2,2,false,true >(sm,smb,rg,jt,t, gi3,pp3,ac3,ds3, T+3*HB, T+4*HB, out);
        grid_bar(rg);
    }
    // Tail: copy final hidden. MUST stay domain-local — rows rg*32..+32 are only
    // guaranteed visible within this CTA's barrier domain. CTA (rg, jt<32)
    // copies row rg*32+jt (512 floats, one per thread).
    if (tail && jt < 32) {
        int row = rg * 32 + jt;
        const float* src = out + (size_t)511 * HB + (size_t)row * 512;
        float* dst = out + (size_t)512 * HB + (size_t)row * 512;
        dst[threadIdx.x] = src[threadIdx.x];
    }
}

extern "C" void kernel_launch(void* const* d_in, const int* in_sizes, int n_in,
                              void* d_out, int out_size) {
    const float* inputs = (const float*)d_in[0];
    const float* hidden = (const float*)d_in[1];
    const float* W0     = (const float*)d_in[2];
    const float* Ws     = (const float*)d_in[3];
    float* out = (float*)d_out;

    prep_kernel<<<577 + 8192, 256>>>(inputs, hidden, W0, Ws);

    cudaFuncSetAttribute(recurrent_kernel,
                         cudaFuncAttributeMaxDynamicSharedMemorySize, SMEM_BYTES);
    int tail = (out_size >= 513 * HB) ? 1 : 0;
    recurrent_kernel<<<128, NTHR, SMEM_BYTES>>>(out, tail);
}

// round 12
// speedup vs baseline: 1.5624x; 1.5624x over previous
#include <cuda_runtime.h>
#include <math.h>
#include <stdint.h>
typedef unsigned long long ull;
typedef uint32_t u32;

#define NTHR 256
#define HB   32768
#define ST_F 0            // state region: 2 bufs * 2 preds * 2048 floats
#define WT_F 8192         // weight region: 2 bufs * NG * 2048 floats (max 16384)
#define SMEM_BYTES 98304

__device__ float g_X[(size_t)512 * 64 * 1024];   // x@W0[:512], [t*64+b][1024]
__device__ float g_T[8][HB];                     // transposed states [slot][col*64+row]; 7=h
__device__ float g_W2[(size_t)576 * 8192];       // [(jt*9+g)][k][ch(2)][j(8)]
__device__ unsigned int g_arr[4], g_gen[4];

__device__ __forceinline__ void fma2(ull &d, ull a, ull b) {
    asm("fma.rn.f32x2 %0, %1, %2, %0;" : "+l"(d) : "l"(a), "l"(b));
}
__device__ __forceinline__ ull dup2(float v) {
    ull r; asm("mov.b64 %0, {%1, %1};" : "=l"(r) : "f"(v)); return r;
}
__device__ __forceinline__ float2 unpk(ull v) {
    float2 f; asm("mov.b64 {%0, %1}, %2;" : "=f"(f.x), "=f"(f.y) : "l"(v)); return f;
}
__device__ __forceinline__ u32 smem_u32(const void* p) {
    u32 a; asm("{ .reg .u64 t; cvta.to.shared.u64 t, %1; cvt.u32.u64 %0, t; }" : "=r"(a) : "l"(p));
    return a;
}
__device__ __forceinline__ void cp16(u32 d, const void* s) {
    asm volatile("cp.async.cg.shared.global [%0], [%1], 16;" :: "r"(d), "l"(s) : "memory");
}
__device__ __forceinline__ float ldcg(const float* p) {
    float v; asm("ld.global.cg.f32 %0, [%1];" : "=f"(v) : "l"(p)); return v;
}
__device__ __forceinline__ void grid_bar(int dom) {
    __syncthreads();
    if (threadIdx.x == 0) {
        unsigned int gen = ((volatile unsigned int*)&g_gen[dom])[0];
        __threadfence();
        if (atomicAdd(&g_arr[dom], 1u) == 63u) {
            g_arr[dom] = 0u; __threadfence();
            ((volatile unsigned int*)&g_gen[dom])[0] = gen + 1u;
        } else {
            while (((volatile unsigned int*)&g_gen[dom])[0] == gen) { }
        }
        __threadfence();
    }
    __syncthreads();
}
__device__ __forceinline__ float actf(int a, float x) {
    if (a == 0) return tanhf(x);
    if (a == 1) return fmaxf(x, 0.f);
    if (a == 2) return 1.f / (1.f + expf(-x));
    return x;
}

// ---------- prep: weight pack + hidden transpose + X precompute ----------
__global__ void __launch_bounds__(256) prep_kernel(const float* __restrict__ A,
    const float* __restrict__ hid, const float* __restrict__ W0, const float* __restrict__ Ws) {
    int bid = blockIdx.x, tid = threadIdx.x;
    if (bid < 576) {                       // pack: bid = jt*9+g -> [k][ch][8j]
        int jt = bid / 9, g = bid % 9;
        const float* src = (g == 8) ? (W0 + (size_t)512 * 1024) : (Ws + (size_t)g * 512 * 1024);
        float* dst = g_W2 + (size_t)bid * 8192;
#pragma unroll
        for (int it = 0; it < 8; ++it) {
            int d4 = (tid + it * 256) * 4;
            int k = d4 >> 4, ch = (d4 >> 3) & 1, jc = d4 & 7;
            *(float4*)(dst + d4) = *(const float4*)(src + (size_t)k * 1024 + ch * 512 + jt * 8 + jc);
        }
        return;
    }
    if (bid == 576) {                      // hT init: g_T[7][col*64+row] = hid[row*512+col]
        for (int i = tid; i < HB; i += 256)
            g_T[7][i] = hid[(size_t)(i & 63) * 512 + (i >> 6)];
        return;
    }
    int idx = bid - 577;                   // X = inputs @ W0[:512]
    __shared__ ull   AsD[64][17];
    __shared__ float Bs[16][68];
    const int n0 = (idx & 15) * 64, m0 = (idx >> 4) * 64;
    const int tx = tid & 15, ty = tid >> 4;
    ull acc[4][2];
#pragma unroll
    for (int i = 0; i < 4; ++i) { acc[i][0] = 0; acc[i][1] = 0; }
    for (int k0 = 0; k0 < 512; k0 += 16) {
        {
            int am = tid >> 2, a4 = tid & 3;
            float4 v = *(const float4*)(A + (size_t)(m0 + am) * 512 + k0 + a4 * 4);
            AsD[am][a4*4+0]=dup2(v.x); AsD[am][a4*4+1]=dup2(v.y);
            AsD[am][a4*4+2]=dup2(v.z); AsD[am][a4*4+3]=dup2(v.w);
        }
        {
            int bk = tid >> 4, b4 = tid & 15;
            *(float4*)&Bs[bk][b4*4] = *(const float4*)(W0 + (size_t)(k0+bk)*1024 + n0 + b4*4);
        }
        __syncthreads();
#pragma unroll
        for (int k = 0; k < 16; ++k) {
            ulonglong2 b = *(const ulonglong2*)&Bs[k][tx*4];
#pragma unroll
            for (int i = 0; i < 4; ++i) { ull a = AsD[ty*4+i][k]; fma2(acc[i][0],a,b.x); fma2(acc[i][1],a,b.y); }
        }
        __syncthreads();
    }
#pragma unroll
    for (int i = 0; i < 4; ++i) {
        float2 lo = unpk(acc[i][0]), hi = unpk(acc[i][1]);
        *(float4*)(g_X + (size_t)(m0+ty*4+i)*1024 + n0 + tx*4) = make_float4(lo.x,lo.y,hi.x,hi.y);
    }
}

// ---------- one DAG level ----------
// CTA: 16 rows (domain rg) x 8 j-cols (jt). 8 warps = K 8-way (64 k each, 16 per chunk).
// lane = row(0..15) + 16*jh; thread computes 4 j x 2 ch as 2 f32x2 per (g,ch).
template<int NG, int NP, bool P0B, bool P3M>
__device__ __forceinline__ void phase(float* sm, u32 smb, int rg, int jt, int t,
    const int* gis, const int* pps, const int* acts, const int* dss,
    const float* pred0, const float* pred1, float* out)
{
    const int tid = threadIdx.x, lane = tid & 31, kq = tid >> 5;
    const int rowl = lane & 15, jh = lane >> 4;
    const bool epi = (tid < 128);
    const int erow = tid & 15, ejc = (tid >> 4) & 7;       // epilogue mapping
    const int ecol = jt * 8 + ejc, egrow = rg * 16 + erow;

    // ---- prefetch epilogue operands (latency hidden behind GEMM) ----
    float pre_sp[NP][1], pre_b[2], pre_m;
    if (epi) {
#pragma unroll
        for (int p = 0; p < NP; ++p)
            pre_sp[p][0] = ldcg((p ? pred1 : pred0) + ecol * 64 + egrow);
        if (P0B) {
            pre_b[0] = ldcg(g_X + ((size_t)t*64 + egrow)*1024 + ecol);
            pre_b[1] = ldcg(g_X + ((size_t)t*64 + egrow)*1024 + 512 + ecol);
        }
        if (P3M) {
            float m = 0.f;
#pragma unroll
            for (int st = 1; st <= 6; ++st) m += ldcg(&g_T[st][ecol*64 + egrow]);
            pre_m = m;
        }
    }

    auto stage = [&](int c, int buf) {
#pragma unroll
        for (int it = 0; it < NP * 2; ++it) {               // states: NP*512 cp16
            int i = tid + it * NTHR, p = i >> 9, rem = i & 511, kl = rem >> 2, seg = rem & 3;
            const float* s = (p ? pred1 : pred0) + (size_t)(c*128 + kl)*64 + rg*16 + seg*4;
            cp16(smb + (u32)(((buf*2 + p)*2048 + kl*16 + seg*4) * 4), s);
        }
#pragma unroll
        for (int it = 0; it < NG * 2; ++it) {               // weights: NG*512 cp16
            int i = tid + it * NTHR, g = i >> 9, rem = i & 511;
            const float* s = g_W2 + (size_t)(jt*9 + gis[g])*8192 + c*2048 + rem*4;
            cp16(smb + (u32)((WT_F + (buf*NG + g)*2048 + rem*4) * 4), s);
        }
        asm volatile("cp.async.commit_group;" ::: "memory");
    };

    ull acc[NG][2][2];
#pragma unroll
    for (int g = 0; g < NG; ++g)
#pragma unroll
        for (int ch = 0; ch < 2; ++ch) { acc[g][ch][0] = 0; acc[g][ch][1] = 0; }

    stage(0, 0);
    for (int c = 0; c < 4; ++c) {
        asm volatile("cp.async.wait_group 0;" ::: "memory");
        __syncthreads();
        if (c < 3) stage(c + 1, (c + 1) & 1);
        const int buf = c & 1;
        const float* sbase = sm + buf*2*2048 + kq*256 + rowl;
        const float* wbase = sm + WT_F + buf*NG*2048 + kq*256 + jh*4;
#pragma unroll
        for (int kk = 0; kk < 16; ++kk) {
            ull sd0 = dup2(sbase[kk * 16]);
            ull sd1 = (NP == 2) ? dup2(sbase[2048 + kk * 16]) : 0ull;
#pragma unroll
            for (int g = 0; g < NG; ++g) {
                const float* wg = wbase + g*2048 + kk*16;
                ulonglong2 wc = *(const ulonglong2*)(wg);        // ch0, 4 j
                ulonglong2 wh = *(const ulonglong2*)(wg + 8);    // ch1, 4 j
                ull sd = (NP == 2 && pps[g]) ? sd1 : sd0;
                fma2(acc[g][0][0], sd, wc.x); fma2(acc[g][0][1], sd, wc.y);
                fma2(acc[g][1][0], sd, wh.x); fma2(acc[g][1][1], sd, wh.y);
            }
        }
    }
    __syncthreads();

    // ---- reduction over 8 K-warps; red overlays dead state region (row-major, conflict-free)
    ull* red = (ull*)sm;
#pragma unroll
    for (int g = 0; g < NG; ++g)
#pragma unroll
        for (int ch = 0; ch < 2; ++ch)
#pragma unroll
            for (int jp = 0; jp < 2; ++jp)
                red[(size_t)((((kq*2 + jh)*NG + g)*4) + ch*2 + jp)*16 + rowl] = acc[g][ch][jp];
    __syncthreads();

    if (epi) {
        const int ejh = ejc >> 2, ejp = (ejc >> 1) & 1, ehalf = ejc & 1;
        float mv = 0.f;
#pragma unroll
        for (int g = 0; g < NG; ++g) {
            float cs = 0.f, hs = 0.f;
#pragma unroll
            for (int q = 0; q < 8; ++q) {
                float2 a = unpk(red[(size_t)((((q*2 + ejh)*NG + g)*4) + 0*2 + ejp)*16 + erow]);
                float2 b = unpk(red[(size_t)((((q*2 + ejh)*NG + g)*4) + 1*2 + ejp)*16 + erow]);
                cs += ehalf ? a.y : a.x;
                hs += ehalf ? b.y : b.x;
            }
            if (P0B) { cs += pre_b[0]; hs += pre_b[1]; }
            float sp = pre_sp[(NP == 2) ? pps[g] : 0][0];
            float cg = 1.f / (1.f + expf(-cs));
            float hv = actf(acts[g], hs);
            float nv = sp + cg * (hv - sp);
            if (!P3M) g_T[dss[g]][ecol*64 + egrow] = nv;
            else mv += nv;
        }
        if (P3M) {
            float m = (pre_m + mv) * 0.125f;
            out[(size_t)t*HB + (size_t)egrow*512 + ecol] = m;
            g_T[7][ecol*64 + egrow] = m;
        }
    }
}

__global__ void __launch_bounds__(NTHR, 2) recurrent_kernel(float* __restrict__ out, int tail)
{
    extern __shared__ float sm[];
    u32 smb = smem_u32(sm);
    const int bid = blockIdx.x, rg = bid >> 6, jt = bid & 63;
    float* T = &g_T[0][0];
    const int gi0[1]={8},       pp0[1]={0},       ac0[1]={0},       ds0[1]={0};
    const int gi1[2]={0,1},     pp1[2]={0,0},     ac1[2]={0,1},     ds1[2]={1,2};
    const int gi2[4]={2,3,4,5}, pp2[4]={0,0,1,1}, ac2[4]={2,3,0,1}, ds2[4]={3,4,5,6};
    const int gi3[2]={6,7},     pp3[2]={0,1},     ac3[2]={2,3},     ds3[2]={0,0};

    for (int t = 0; t < 512; ++t) {
        phase<1,1,true ,false>(sm,smb,rg,jt,t, gi0,pp0,ac0,ds0, T+7*HB, nullptr, out);
        grid_bar(rg);
        phase<2,1,false,false>(sm,smb,rg,jt,t, gi1,pp1,ac1,ds1, T+0*HB, nullptr, out);
        grid_bar(rg);
        phase<4,2,false,false>(sm,smb,rg,jt,t, gi2,pp2,ac2,ds2, T+1*HB, T+2*HB, out);
        grid_bar(rg);
        phase<2,2,false,true >(sm,smb,rg,jt,t, gi3,pp3,ac3,ds3, T+3*HB, T+4*HB, out);
        grid_bar(rg);
    }
    // tail: domain-local copy of final hidden (rows rg*16..+16 only)
    if (tail && jt < 16) {
        int row = rg * 16 + jt;
        const float* src = out + (size_t)511 * HB + (size_t)row * 512;
        float* dst = out + (size_t)512 * HB + (size_t)row * 512;
        dst[threadIdx.x]       = src[threadIdx.x];
        dst[threadIdx.x + 256] = src[threadIdx.x + 256];
    }
}

extern "C" void kernel_launch(void* const* d_in, const int* in_sizes, int n_in,
                              void* d_out, int out_size) {
    const float* inputs = (const float*)d_in[0];
    const float* hidden = (const float*)d_in[1];
    const float* W0     = (const float*)d_in[2];
    const float* Ws     = (const float*)d_in[3];
    float* out = (float*)d_out;

    prep_kernel<<<577 + 8192, 256>>>(inputs, hidden, W0, Ws);

    cudaFuncSetAttribute(recurrent_kernel,
                         cudaFuncAttributeMaxDynamicSharedMemorySize, SMEM_BYTES);
    int tail = (out_size >= 513 * HB) ? 1 : 0;
    recurrent_kernel<<<256, NTHR, SMEM_BYTES>>>(out, tail);
}

// round 14
// speedup vs baseline: 1.5774x; 1.0096x over previous
#include <cuda_runtime.h>
#include <math.h>
#include <stdint.h>
typedef unsigned long long ull;
typedef uint32_t u32;

#define NTHR 512
#define HB   32768
#define HALF_F 24576              // floats per half region (96KB)
#define WT_F   8192               // weight offset within half (floats)
#define SMEM_BYTES 196608

__device__ float g_X[(size_t)512 * 64 * 1024];   // x@W0[:512], [t*64+b][1024]
__device__ float g_T[8][HB];                     // transposed states [slot][col*64+row]; 7=h
__device__ float g_W2[(size_t)576 * 8192];       // [(jt*9+g)][k][ch(2)][j(8)]
__device__ unsigned int g_arr[4], g_gen[4];

__device__ __forceinline__ void fma2(ull &d, ull a, ull b) {
    asm("fma.rn.f32x2 %0, %1, %2, %0;" : "+l"(d) : "l"(a), "l"(b));
}
__device__ __forceinline__ ull dup2(float v) {
    ull r; asm("mov.b64 %0, {%1, %1};" : "=l"(r) : "f"(v)); return r;
}
__device__ __forceinline__ float2 unpk(ull v) {
    float2 f; asm("mov.b64 {%0, %1}, %2;" : "=f"(f.x), "=f"(f.y) : "l"(v)); return f;
}
__device__ __forceinline__ u32 smem_u32(const void* p) {
    u32 a; asm("{ .reg .u64 t; cvta.to.shared.u64 t, %1; cvt.u32.u64 %0, t; }" : "=r"(a) : "l"(p));
    return a;
}
__device__ __forceinline__ void cp16(u32 d, const void* s) {
    asm volatile("cp.async.cg.shared.global [%0], [%1], 16;" :: "r"(d), "l"(s) : "memory");
}
__device__ __forceinline__ float ldcg(const float* p) {
    float v; asm("ld.global.cg.f32 %0, [%1];" : "=f"(v) : "l"(p)); return v;
}
__device__ __forceinline__ void half_bar(int h) {
    asm volatile("bar.sync %0, 256;" :: "r"(h + 1) : "memory");
}
__device__ __forceinline__ void grid_bar2(int dom, int h) {
    half_bar(h);
    if ((threadIdx.x & 255) == 0) {
        unsigned int gen = ((volatile unsigned int*)&g_gen[dom])[0];
        __threadfence();
        if (atomicAdd(&g_arr[dom], 1u) == 63u) {
            g_arr[dom] = 0u; __threadfence();
            ((volatile unsigned int*)&g_gen[dom])[0] = gen + 1u;
        } else {
            while (((volatile unsigned int*)&g_gen[dom])[0] == gen) { }
        }
        __threadfence();
    }
    half_bar(h);
}
__device__ __forceinline__ float sigm_f(float x) {
    return __fdividef(1.f, 1.f + __expf(-x));
}
__device__ __forceinline__ float actf(int a, float x) {
    if (a == 0) {                                  // tanh, overflow-safe
        float ax = fabsf(x);
        float e = __expf(-2.f * ax);
        float r = __fdividef(1.f - e, 1.f + e);
        return copysignf(r, x);
    }
    if (a == 1) return fmaxf(x, 0.f);
    if (a == 2) return sigm_f(x);
    return x;
}

// ---------- prep: weight pack + hidden transpose + X precompute ----------
__global__ void __launch_bounds__(256) prep_kernel(const float* __restrict__ A,
    const float* __restrict__ hid, const float* __restrict__ W0, const float* __restrict__ Ws) {
    int bid = blockIdx.x, tid = threadIdx.x;
    if (bid < 576) {                       // pack: bid = jt*9+g -> [k][ch][8j]
        int jt = bid / 9, g = bid % 9;
        const float* src = (g == 8) ? (W0 + (size_t)512 * 1024) : (Ws + (size_t)g * 512 * 1024);
        float* dst = g_W2 + (size_t)bid * 8192;
#pragma unroll
        for (int it = 0; it < 8; ++it) {
            int d4 = (tid + it * 256) * 4;
            int k = d4 >> 4, ch = (d4 >> 3) & 1, jc = d4 & 7;
            *(float4*)(dst + d4) = *(const float4*)(src + (size_t)k * 1024 + ch * 512 + jt * 8 + jc);
        }
        return;
    }
    if (bid == 576) {                      // hT init
        for (int i = tid; i < HB; i += 256)
            g_T[7][i] = hid[(size_t)(i & 63) * 512 + (i >> 6)];
        return;
    }
    int idx = bid - 577;                   // X = inputs @ W0[:512]
    __shared__ ull   AsD[64][17];
    __shared__ float Bs[16][68];
    const int n0 = (idx & 15) * 64, m0 = (idx >> 4) * 64;
    const int tx = tid & 15, ty = tid >> 4;
    ull acc[4][2];
#pragma unroll
    for (int i = 0; i < 4; ++i) { acc[i][0] = 0; acc[i][1] = 0; }
    for (int k0 = 0; k0 < 512; k0 += 16) {
        {
            int am = tid >> 2, a4 = tid & 3;
            float4 v = *(const float4*)(A + (size_t)(m0 + am) * 512 + k0 + a4 * 4);
            AsD[am][a4*4+0]=dup2(v.x); AsD[am][a4*4+1]=dup2(v.y);
            AsD[am][a4*4+2]=dup2(v.z); AsD[am][a4*4+3]=dup2(v.w);
        }
        {
            int bk = tid >> 4, b4 = tid & 15;
            *(float4*)&Bs[bk][b4*4] = *(const float4*)(W0 + (size_t)(k0+bk)*1024 + n0 + b4*4);
        }
        __syncthreads();
#pragma unroll
        for (int k = 0; k < 16; ++k) {
            ulonglong2 b = *(const ulonglong2*)&Bs[k][tx*4];
#pragma unroll
            for (int i = 0; i < 4; ++i) { ull a = AsD[ty*4+i][k]; fma2(acc[i][0],a,b.x); fma2(acc[i][1],a,b.y); }
        }
        __syncthreads();
    }
#pragma unroll
    for (int i = 0; i < 4; ++i) {
        float2 lo = unpk(acc[i][0]), hi = unpk(acc[i][1]);
        *(float4*)(g_X + (size_t)(m0+ty*4+i)*1024 + n0 + tx*4) = make_float4(lo.x,lo.y,hi.x,hi.y);
    }
}

// ---------- one DAG level for one half (16 rows x 8 j, NP=1, single stage) ----------
template<int NG, bool BIAS, bool MEAN, bool S7>
__device__ __forceinline__ void phase(float* smh, u32 smhb, int dom, int jt, int t,
    int gi0, int gi1, int ac0, int ac1, int ds0, int ds1,
    const float* pred, float* out, float& s7reg, int h)
{
    const int tid = threadIdx.x & 255;
    const int lane = tid & 31, kq = tid >> 5;
    const int rowl = lane & 15, jh = lane >> 4;
    const bool epi = (tid < 128);
    const int erow = tid & 15, ejc = (tid >> 4) & 7;
    const int ecol = jt * 8 + ejc, egrow = dom * 16 + erow;

    // epilogue operand prefetch (hidden behind GEMM)
    float pre_sp = 0.f, pre_b0 = 0.f, pre_b1 = 0.f, pre_m = 0.f;
    if (epi) {
        pre_sp = ldcg(pred + (size_t)ecol * 64 + egrow);
        if (BIAS) {
            pre_b0 = ldcg(g_X + ((size_t)t * 64 + egrow) * 1024 + ecol);
            pre_b1 = ldcg(g_X + ((size_t)t * 64 + egrow) * 1024 + 512 + ecol);
        }
        if (MEAN) {
            float m = 0.f;
#pragma unroll
            for (int st = 1; st <= 6; ++st) m += ldcg(&g_T[st][(size_t)ecol * 64 + egrow]);
            pre_m = m;
        }
    }

    // single-shot stage: states [k512][16 rows] + weights NG*[k][ch][8j]
#pragma unroll
    for (int it = 0; it < 8; ++it) {
        int i = tid + it * 256, k = i >> 2, seg = i & 3;
        cp16(smhb + (u32)((k * 16 + seg * 4) * 4),
             pred + (size_t)k * 64 + dom * 16 + seg * 4);
    }
#pragma unroll
    for (int it = 0; it < NG * 8; ++it) {
        int i = tid + it * 256, g = i >> 11, rem = i & 2047;
        int gi = g ? gi1 : gi0;
        cp16(smhb + (u32)((WT_F + g * 8192 + rem * 4) * 4),
             g_W2 + (size_t)(jt * 9 + gi) * 8192 + rem * 4);
    }
    asm volatile("cp.async.commit_group;" ::: "memory");
    asm volatile("cp.async.wait_group 0;" ::: "memory");
    half_bar(h);

    // compute: warp kq handles k in [kq*64, kq*64+64)
    ull acc[NG][2][2];
#pragma unroll
    for (int g = 0; g < NG; ++g)
#pragma unroll
        for (int ch = 0; ch < 2; ++ch) { acc[g][ch][0] = 0; acc[g][ch][1] = 0; }
    const float* sbase = smh + kq * 64 * 16 + rowl;
    const float* wb    = smh + WT_F + kq * 64 * 16 + jh * 4;
#pragma unroll 8
    for (int kk = 0; kk < 64; ++kk) {
        ull sd = dup2(sbase[kk * 16]);
#pragma unroll
        for (int g = 0; g < NG; ++g) {
            const float* wg = wb + g * 8192 + kk * 16;
            ulonglong2 wc = *(const ulonglong2*)(wg);
            ulonglong2 wh = *(const ulonglong2*)(wg + 8);
            fma2(acc[g][0][0], sd, wc.x); fma2(acc[g][0][1], sd, wc.y);
            fma2(acc[g][1][0], sd, wh.x); fma2(acc[g][1][1], sd, wh.y);
        }
    }
    half_bar(h);

    // reduction over 8 K-warps; red overlays the (dead) weight region
    ull* red = (ull*)(smh + WT_F);
#pragma unroll
    for (int g = 0; g < NG; ++g)
#pragma unroll
        for (int ch = 0; ch < 2; ++ch)
#pragma unroll
            for (int jp = 0; jp < 2; ++jp)
                red[(size_t)((((kq*2 + jh)*NG + g)*4) + ch*2 + jp)*16 + rowl] = acc[g][ch][jp];
    half_bar(h);

    if (epi) {
        const int ejh = ejc >> 2, ejp = (ejc >> 1) & 1, ehalf = ejc & 1;
        float mv = 0.f;
#pragma unroll
        for (int g = 0; g < NG; ++g) {
            float cs = 0.f, hs = 0.f;
#pragma unroll
            for (int q = 0; q < 8; ++q) {
                float2 a = unpk(red[(size_t)((((q*2 + ejh)*NG + g)*4) + 0 + ejp)*16 + erow]);
                float2 b = unpk(red[(size_t)((((q*2 + ejh)*NG + g)*4) + 2 + ejp)*16 + erow]);
                cs += ehalf ? a.y : a.x;
                hs += ehalf ? b.y : b.x;
            }
            if (BIAS) { cs += pre_b0; hs += pre_b1; }
            int act = g ? ac1 : ac0;
            float cg = sigm_f(cs);
            float hv = actf(act, hs);
            float nv = pre_sp + cg * (hv - pre_sp);
            if (S7) s7reg = nv;
            else if (!MEAN) g_T[g ? ds1 : ds0][(size_t)ecol * 64 + egrow] = nv;
            if (MEAN) mv += nv;
        }
        if (MEAN) {
            float m = (pre_m + s7reg + mv) * 0.125f;
            out[(size_t)t * HB + (size_t)egrow * 512 + ecol] = m;
            g_T[7][(size_t)ecol * 64 + egrow] = m;
        }
    }
    // Order epilogue's reads of `red` (weight region) before the NEXT phase's
    // cp.async staging writes into that same region. Without this, paired
    // phases (P2a->P2b, P3a->P3b) race and corrupt results.
    half_bar(h);
}

__global__ void __launch_bounds__(NTHR, 1) recurrent_kernel(float* __restrict__ out, int tail)
{
    extern __shared__ float sm[];
    const int h = threadIdx.x >> 8;                 // half 0/1
    float* smh = sm + h * HALF_F;
    u32 smhb = smem_u32(smh);
    const int bid = blockIdx.x, jt = bid & 63, dp = bid >> 6;
    const int dom = dp * 2 + h;                     // this half's row domain (16 rows)
    float* T = &g_T[0][0];
    float s7 = 0.f;

    for (int t = 0; t < 512; ++t) {
        // P0: s0 = h + sig(c)*(tanh(hh)-h); gemm 8, bias X[t]
        phase<1, true , false, false>(smh, smhb, dom, jt, t, 8, 0, 0, 0, 0, 0,
                                      T + 7*HB, out, s7, h);
        grid_bar2(dom, h);
        // P1: s1(tanh), s2(relu) from s0
        phase<2, false, false, false>(smh, smhb, dom, jt, t, 0, 1, 0, 1, 1, 2,
                                      T + 0*HB, out, s7, h);
        grid_bar2(dom, h);
        // P2a: s3(sig), s4(id) from s1 ; P2b: s5(tanh), s6(relu) from s2
        phase<2, false, false, false>(smh, smhb, dom, jt, t, 2, 3, 2, 3, 3, 4,
                                      T + 1*HB, out, s7, h);
        phase<2, false, false, false>(smh, smhb, dom, jt, t, 4, 5, 0, 1, 5, 6,
                                      T + 2*HB, out, s7, h);
        grid_bar2(dom, h);
        // P3a: s7(sig) from s3 (kept in reg) ; P3b: s8(id) from s4 + mean -> out[t]
        phase<1, false, false, true >(smh, smhb, dom, jt, t, 6, 0, 2, 0, 0, 0,
                                      T + 3*HB, out, s7, h);
        phase<1, false, true , false>(smh, smhb, dom, jt, t, 7, 0, 3, 0, 0, 0,
                                      T + 4*HB, out, s7, h);
        grid_bar2(dom, h);
    }
    // tail: domain-local copy of final hidden (rows dom*16..+16)
    if (tail && jt < 16) {
        int row = dom * 16 + jt;
        const float* src = out + (size_t)511 * HB + (size_t)row * 512;
        float* dst = out + (size_t)512 * HB + (size_t)row * 512;
        int tl = threadIdx.x & 255;
        dst[tl]       = src[tl];
        dst[tl + 256] = src[tl + 256];
    }
}

extern "C" void kernel_launch(void* const* d_in, const int* in_sizes, int n_in,
                              void* d_out, int out_size) {
    const float* inputs = (const float*)d_in[0];
    const float* hidden = (const float*)d_in[1];
    const float* W0     = (const float*)d_in[2];
    const float* Ws     = (const float*)d_in[3];
    float* out = (float*)d_out;

    prep_kernel<<<577 + 8192, 256>>>(inputs, hidden, W0, Ws);

    cudaFuncSetAttribute(recurrent_kernel,
                         cudaFuncAttributeMaxDynamicSharedMemorySize, SMEM_BYTES);
    int tail = (out_size >= 513 * HB) ? 1 : 0;
    recurrent_kernel<<<128, NTHR, SMEM_BYTES>>>(out, tail);
}